// round 11
// baseline (speedup 1.0000x reference)
#include <cuda_runtime.h>
#include <cstdint>
#include <math.h>

// IMDCT round 11: symmetry-halved + two-stage Cooley-Tukey + radix-2 butterfly stage 1.
//
//   z_col[t] = sum_u W2[t][u] * PQ[u][tau],  tau = t & 31,  u in [0,32)
//   PQ[f0][tau]=P, PQ[16+f0][tau]=Q;  P/Q[tau] = E +/- O (even/odd-f1 partial sums),
//   using C1[tau+16][f1] = (-1)^f1 C1[tau][f1] (same for S1).
//   W2 from input kernels (round-10 identities). Output = windowed overlap-add.
//
// Block 128 thr = 4 warps, NSEG=31 segs, 32 spec cols. 4 chunks x 8 cols; warp w owns
// cols (2w, 2w+1) of each chunk end-to-end (stage1 -> PQ -> stage2 -> Dt), so the main
// loop needs only __syncwarp. Stage 1: lane = (col-half c', tau-base g); 16B spec
// broadcast feeds 16 FMA2 across 2 cols. PQ: u-stride 33, col-stride 1072 (=16 mod 32)
// -> all PQ stores/loads 1 wavefront. Stage 2: z packed over col-pairs, weights from
// prepacked {w,w} b64 table (L1-resident, 64KB).

#define NFREQ    256
#define TFRAMES  4096
#define NSEG     31
#define NCOLS    32
#define TSTR     260        // smT/Dt col stride (words), 16B-aligned rows
#define USTR     33         // PQ u-stride (words)
#define PQCOL    1072       // PQ per-col buffer (words); 1072 % 32 == 16 (bank offset)
#define SMWORDS  (NCOLS * TSTR)          // 8320
#define PQWORDS  (8 * PQCOL)             // 8576
#define SMBYTES  ((SMWORDS + PQWORDS) * 4)   // 67,584
#define LOUT     1048832

#define FMA2(acc, a, v) \
    asm("fma.rn.f32x2 %0, %1, %2, %0;" : "+l"(acc) : "l"(a), "l"(v))
#define PACK2(dst, x) \
    asm("mov.b64 %0, {%1, %1};" : "=l"(dst) : "r"(__float_as_uint(x)))

__device__ unsigned long long g_w2p[32 * 32 * 8];  // [(u*32+tau)*8+m] = {W2[t],W2[t]}, t=tau+32m
__device__ float g_c1s1[32 * 32];                  // [tau][j]: j<16 C1, j>=16 S1
__device__ float g_win[512];

__global__ void prep_kernel(const float* __restrict__ kernels)
{
    int idx = blockIdx.x * blockDim.x + threadIdx.x;   // 10240 threads
    if (idx < 8192) {                                  // g_w2p: idx = u*256 + tau*8 + m
        int m = idx & 7, tau = (idx >> 3) & 31, u = idx >> 8;
        int t = tau + 32 * m;
        double wn = sin(M_PI * (2.0 * (128 + t) + 1.0) / 1024.0);
        double sc = 1.0 / (128.0 * wn);
        float w;
        if (u < 16)
            w = (float)((double)kernels[(128 + t) * 256 + u] * sc);
        else {
            float sgn = (t & 1) ? 1.0f : -1.0f;        // -(-1)^t
            w = sgn * (float)((double)kernels[(128 + t) * 256 + (255 - (u - 16))] * sc);
        }
        unsigned long long p = ((unsigned long long)__float_as_uint(w) << 32) | __float_as_uint(w);
        g_w2p[idx] = p;
    } else if (idx < 9216) {                           // g_c1s1
        int i = idx - 8192;
        int tau = i >> 5, j = i & 31, f1 = j & 15;
        double ang = M_PI * (2.0 * tau + 513.0) * (double)f1 / 32.0;
        g_c1s1[tau * 32 + j] = (float)((j < 16) ? cos(ang) : sin(ang));
    } else if (idx < 9728) {
        int t = idx - 9216;
        g_win[t] = (float)sin(M_PI * (2.0 * t + 1.0) / 1024.0);
    }
}

__global__ __launch_bounds__(128, 3)
void imdct_main_kernel(const float* __restrict__ spec, float* __restrict__ out)
{
    extern __shared__ float sm[];                      // smT[32][260] ++ PQ[8][1072]
    const int tid  = threadIdx.x;
    const int lane = tid & 31;
    const int w    = tid >> 5;                         // warp 0..3
    const int cp   = lane >> 4;                        // stage-1 col half 0/1
    const int g    = lane & 15;                        // tau base (tau = g, g+16)
    const int b    = blockIdx.y;
    const int s0   = blockIdx.x * NSEG;

    // ---- Stage spec transposed: smT[c][f] = spec[b][f][s0-1+c] ----
    const float* specB = spec + (size_t)b * NFREQ * TFRAMES;
    for (int i = tid; i < NFREQ * NCOLS; i += 128) {
        int f = i >> 5, c = i & 31;
        int cg = s0 - 1 + c;
        float v = (cg >= 0 && cg < TFRAMES) ? __ldg(&specB[(size_t)f * TFRAMES + cg]) : 0.0f;
        sm[c * TSTR + f] = v;
    }

    // ---- Stage-1 trig for tau = g ----
    float c1[16], s1[16];
    {
        const float4* cp4 = (const float4*)(g_c1s1 + g * 32);
        #pragma unroll
        for (int q = 0; q < 4; q++) {
            float4 a = __ldg(&cp4[q]);
            c1[4*q] = a.x; c1[4*q+1] = a.y; c1[4*q+2] = a.z; c1[4*q+3] = a.w;
        }
        #pragma unroll
        for (int q = 0; q < 4; q++) {
            float4 a = __ldg(&cp4[4 + q]);
            s1[4*q] = a.x; s1[4*q+1] = a.y; s1[4*q+2] = a.z; s1[4*q+3] = a.w;
        }
    }

    const uint32_t smb = (uint32_t)__cvta_generic_to_shared(sm);
    const uint32_t pqb = smb + SMWORDS * 4;
    __syncthreads();

    #pragma unroll 1
    for (int ch = 0; ch < 4; ch++) {
        // ======== stage 1: lane computes E/O sums for col cc, taus (g, g+16) ========
        const int cc = 8 * ch + 2 * w + cp;
        unsigned long long PE[8], PO[8], QE[8], QO[8];
        #pragma unroll
        for (int p = 0; p < 8; p++) { PE[p]=0; PO[p]=0; QE[p]=0; QO[p]=0; }

        const uint32_t colb = smb + (uint32_t)(cc * (TSTR * 4));
        #pragma unroll
        for (int f1 = 0; f1 < 16; f1++) {
            unsigned long long v[8];
            #pragma unroll
            for (int q = 0; q < 4; q++)
                asm volatile("ld.shared.v2.b64 {%0, %1}, [%2];"
                             : "=l"(v[2*q]), "=l"(v[2*q+1])
                             : "r"(colb + f1 * 64 + q * 16));
            unsigned long long cpk, spk;
            PACK2(cpk, c1[f1]); PACK2(spk, s1[f1]);
            if ((f1 & 1) == 0) {
                #pragma unroll
                for (int p = 0; p < 8; p++) { FMA2(PE[p], cpk, v[p]); FMA2(QE[p], spk, v[p]); }
            } else {
                #pragma unroll
                for (int p = 0; p < 8; p++) { FMA2(PO[p], cpk, v[p]); FMA2(QO[p], spk, v[p]); }
            }
        }

        // ---- butterfly + PQ store (1-wavefront: banks = 16*cp + g + const) ----
        const uint32_t pqc = pqb + (uint32_t)((2 * w + cp) * PQCOL * 4);
        #pragma unroll
        for (int p = 0; p < 8; p++) {
            float pel = __uint_as_float((uint32_t)PE[p]), peh = __uint_as_float((uint32_t)(PE[p] >> 32));
            float pol = __uint_as_float((uint32_t)PO[p]), poh = __uint_as_float((uint32_t)(PO[p] >> 32));
            float qel = __uint_as_float((uint32_t)QE[p]), qeh = __uint_as_float((uint32_t)(QE[p] >> 32));
            float qol = __uint_as_float((uint32_t)QO[p]), qoh = __uint_as_float((uint32_t)(QO[p] >> 32));
            uint32_t uP0 = pqc + (uint32_t)(((2*p)     * USTR + g) * 4);
            uint32_t uP1 = pqc + (uint32_t)(((2*p + 1) * USTR + g) * 4);
            uint32_t uQ0 = pqc + (uint32_t)(((16 + 2*p)     * USTR + g) * 4);
            uint32_t uQ1 = pqc + (uint32_t)(((16 + 2*p + 1) * USTR + g) * 4);
            asm volatile("st.shared.b32 [%0], %1;" :: "r"(uP0),      "r"(__float_as_uint(pel + pol)));
            asm volatile("st.shared.b32 [%0], %1;" :: "r"(uP0 + 64), "r"(__float_as_uint(pel - pol)));
            asm volatile("st.shared.b32 [%0], %1;" :: "r"(uP1),      "r"(__float_as_uint(peh + poh)));
            asm volatile("st.shared.b32 [%0], %1;" :: "r"(uP1 + 64), "r"(__float_as_uint(peh - poh)));
            asm volatile("st.shared.b32 [%0], %1;" :: "r"(uQ0),      "r"(__float_as_uint(qel + qol)));
            asm volatile("st.shared.b32 [%0], %1;" :: "r"(uQ0 + 64), "r"(__float_as_uint(qel - qol)));
            asm volatile("st.shared.b32 [%0], %1;" :: "r"(uQ1),      "r"(__float_as_uint(qeh + qoh)));
            asm volatile("st.shared.b32 [%0], %1;" :: "r"(uQ1 + 64), "r"(__float_as_uint(qeh - qoh)));
        }
        __syncwarp();

        // ======== stage 2: z packed over cols (8ch+2w, 8ch+2w+1), t = lane + 32m ========
        unsigned long long z2[8];
        #pragma unroll
        for (int m = 0; m < 8; m++) z2[m] = 0;
        const uint32_t pqA = pqb + (uint32_t)((2 * w) * PQCOL * 4);
        const uint32_t pqB = pqA + PQCOL * 4;
        const unsigned long long* __restrict__ wrow = g_w2p + lane * 8;

        #pragma unroll 8
        for (int u = 0; u < 32; u++) {
            uint32_t va, vb;
            uint32_t off = (uint32_t)((u * USTR + lane) * 4);
            asm volatile("ld.shared.b32 %0, [%1];" : "=r"(va) : "r"(pqA + off));
            asm volatile("ld.shared.b32 %0, [%1];" : "=r"(vb) : "r"(pqB + off));
            unsigned long long vq;
            asm("mov.b64 %0, {%1, %2};" : "=l"(vq) : "r"(va), "r"(vb));
            const ulonglong2* wu = (const ulonglong2*)(wrow + (size_t)u * 256);
            ulonglong2 w01 = __ldg(&wu[0]);
            ulonglong2 w23 = __ldg(&wu[1]);
            ulonglong2 w45 = __ldg(&wu[2]);
            ulonglong2 w67 = __ldg(&wu[3]);
            FMA2(z2[0], w01.x, vq); FMA2(z2[1], w01.y, vq);
            FMA2(z2[2], w23.x, vq); FMA2(z2[3], w23.y, vq);
            FMA2(z2[4], w45.x, vq); FMA2(z2[5], w45.y, vq);
            FMA2(z2[6], w67.x, vq); FMA2(z2[7], w67.y, vq);
        }

        // ---- Dt overlay into the (dead, warp-private) smT cols ----
        const int ca = 8 * ch + 2 * w;
        #pragma unroll
        for (int m = 0; m < 8; m++) {
            int t = lane + 32 * m;
            sm[ca * TSTR + t]       = __uint_as_float((uint32_t)z2[m]);
            sm[(ca + 1) * TSTR + t] = __uint_as_float((uint32_t)(z2[m] >> 32));
        }
        __syncwarp();
    }
    __syncthreads();

    // ---- Windowed overlap-add epilogue: 4 consecutive k/thread ----
    {
        const int lt = tid & 63;
        const int h  = tid >> 6;                       // segment half
        const int k0 = 4 * lt;                         // 0..252
        const bool lo = (lt < 32);                     // warp-uniform
        float wA[4], wB[4];
        #pragma unroll
        for (int d = 0; d < 4; d++) {
            int k = k0 + d;
            wA[d] = __ldg(&g_win[k]) * (lo ? -1.0f : 1.0f);
            wB[d] = __ldg(&g_win[k + 256]);
        }
        const int aOff = lo ? (124 - k0) : (k0 - 128);
        const int bOff = lo ? (k0 + 128) : (380 - k0);
        float* ob = out + (size_t)b * LOUT + k0;

        #pragma unroll 4
        for (int ii = 0; ii < 16; ii++) {
            int i = 16 * h + ii;                       // 0..15 / 16..31
            int s = s0 + i;
            if (i < NSEG && s <= 4096) {
                float4 a4 = *reinterpret_cast<const float4*>(sm + (i + 1) * TSTR + aOff);
                float4 b4 = *reinterpret_cast<const float4*>(sm + i * TSTR + bOff);
                float av[4], bv[4];
                if (lo) { av[0]=a4.w; av[1]=a4.z; av[2]=a4.y; av[3]=a4.x;
                          bv[0]=b4.x; bv[1]=b4.y; bv[2]=b4.z; bv[3]=b4.w; }
                else    { av[0]=a4.x; av[1]=a4.y; av[2]=a4.z; av[3]=a4.w;
                          bv[0]=b4.w; bv[1]=b4.z; bv[2]=b4.y; bv[3]=b4.x; }
                float4 o;
                o.x = wA[0] * av[0] + wB[0] * bv[0];
                o.y = wA[1] * av[1] + wB[1] * bv[1];
                o.z = wA[2] * av[2] + wB[2] * bv[2];
                o.w = wA[3] * av[3] + wB[3] * bv[3];
                *reinterpret_cast<float4*>(ob + (size_t)s * 256) = o;
            }
        }
    }
}

extern "C" void kernel_launch(void* const* d_in, const int* in_sizes, int n_in,
                              void* d_out, int out_size)
{
    const float* spec    = (const float*)d_in[0];   // [16,1,256,4096]
    const float* kernels = (const float*)d_in[1];   // [512,256]
    float* out = (float*)d_out;                     // [16,1048832]

    prep_kernel<<<40, 256>>>(kernels);              // 10240 threads

    cudaFuncSetAttribute(imdct_main_kernel,
                         cudaFuncAttributeMaxDynamicSharedMemorySize, SMBYTES);
    dim3 grid((4097 + NSEG - 1) / NSEG, 16);        // (133, 16)
    imdct_main_kernel<<<grid, 128, SMBYTES>>>(spec, out);
}

// round 12
// speedup vs baseline: 2.0662x; 2.0662x over previous
#include <cuda_runtime.h>
#include <cstdint>
#include <math.h>

// IMDCT round 12: symmetry-halved + two-stage Cooley-Tukey, stage-1 radix-2 butterfly,
// stage-2 packed over 4 columns, conflict-free PQ.
//
//   z_col[t] = sum_u W2[t][u]*PQ[u][tau],  tau=t&31
//   PQ[f0][.]=P, PQ[16+f0][.]=Q, built as E +/- O (even/odd f1) via
//   C1[tau+16][f1] = (-1)^f1 C1[tau][f1].  W2 from input kernels (R10 identities).
//   out[b, s*256+k] = win[k]*(k<128 ? -z_s[127-k] : z_s[k-128])
//                   + win[k+256]*(k<128 ? z_{s-1}[k+128] : z_{s-1}[383-k])
//
// Block 64 thr (2 warps), NSEG=18 segs, 20 spec cols = 5 groups of 4.
// Per group: stage-1 (warp w, lane=(cp,g): col 4G+2w+cp, taus g/g+16 via butterfly;
// 16B spec broadcasts amortized over 2 cols), sync, stage-2 (block-wide: 4 cols packed,
// R10 float4 weight table, 1-wf PQ loads), Dt overlay into dead smT cols, sync.

#define NFREQ    256
#define TFRAMES  4096
#define NSEG     18
#define NCOLS    20
#define TSTR     260                      // smT/Dt col stride (words)
#define SMTW     (NCOLS * TSTR)           // 5200 words
#define PQCOLW   1072                     // PQ per-col stride (words); 1072%32==16
#define SMWORDS  (SMTW + 4 * PQCOLW)      // 9488
#define SMBYTES  (SMWORDS * 4)            // 37,952 B
#define LOUT     1048832

#define FMA2(acc, a, v) \
    asm("fma.rn.f32x2 %0, %1, %2, %0;" : "+l"(acc) : "l"(a), "l"(v))
#define PACK2(dst, x) \
    asm("mov.b64 %0, {%1, %1};" : "=l"(dst) : "r"(__float_as_uint(x)))

__device__ float4 g_w2[32 * 64];    // [u][tid]: {W2[t], W2[t+64], W2[t+128], W2[t+192]}
__device__ float  g_c1s1[32 * 32];  // [tau][j]: j<16 -> C1, j>=16 -> S1
__device__ float  g_win[512];

__global__ void prep_kernel(const float* __restrict__ kernels)
{
    int idx = blockIdx.x * blockDim.x + threadIdx.x;   // 4096 threads
    if (idx < 2048) {                                  // g_w2
        int u = idx >> 6, tid = idx & 63;
        float r[4];
        #pragma unroll
        for (int m = 0; m < 4; m++) {
            int t = tid + 64 * m;
            double wn = sin(M_PI * (2.0 * (128 + t) + 1.0) / 1024.0);
            double sc = 1.0 / (128.0 * wn);
            if (u < 16)
                r[m] = (float)((double)kernels[(128 + t) * 256 + u] * sc);
            else {
                float sgn = (t & 1) ? 1.0f : -1.0f;    // -(-1)^t
                r[m] = sgn * (float)((double)kernels[(128 + t) * 256 + (255 - (u - 16))] * sc);
            }
        }
        g_w2[u * 64 + tid] = make_float4(r[0], r[1], r[2], r[3]);
    } else if (idx < 3072) {                           // g_c1s1
        int i = idx - 2048;
        int tau = i >> 5, j = i & 31, f1 = j & 15;
        double ang = M_PI * (2.0 * tau + 513.0) * (double)f1 / 32.0;
        g_c1s1[tau * 32 + j] = (float)((j < 16) ? cos(ang) : sin(ang));
    } else if (idx < 3584) {
        int t = idx - 3072;
        g_win[t] = (float)sin(M_PI * (2.0 * t + 1.0) / 1024.0);
    }
}

__global__ __launch_bounds__(64, 6)
void imdct_main_kernel(const float* __restrict__ spec, float* __restrict__ out)
{
    extern __shared__ float sm[];                      // smT[20][260] ++ PQ[4][1072]
    const int tid  = threadIdx.x;                      // 0..63
    const int lane = tid & 31;
    const int w    = tid >> 5;                         // warp 0/1
    const int cp   = lane >> 4;                        // stage-1 col select within warp
    const int g    = lane & 15;                        // tau base (taus g, g+16)
    const int b    = blockIdx.y;
    const int s0   = blockIdx.x * NSEG;

    // ---- Stage spec transposed: smT[c][f] = spec[b][f][s0-1+c], zero-fill edges ----
    const float* specB = spec + (size_t)b * NFREQ * TFRAMES;
    for (int i = tid; i < NFREQ * NCOLS; i += 64) {
        int f = i / NCOLS, c = i - f * NCOLS;
        int cg = s0 - 1 + c;
        float v = (cg >= 0 && cg < TFRAMES) ? __ldg(&specB[(size_t)f * TFRAMES + cg]) : 0.0f;
        sm[c * TSTR + f] = v;
    }

    // ---- Stage-1 trig for tau = g (rows 0..15 of table) ----
    float c1[16], s1[16];
    {
        const float4* cp4 = (const float4*)(g_c1s1 + g * 32);
        #pragma unroll
        for (int q = 0; q < 4; q++) {
            float4 a = __ldg(&cp4[q]);
            c1[4*q] = a.x; c1[4*q+1] = a.y; c1[4*q+2] = a.z; c1[4*q+3] = a.w;
        }
        #pragma unroll
        for (int q = 0; q < 4; q++) {
            float4 a = __ldg(&cp4[4 + q]);
            s1[4*q] = a.x; s1[4*q+1] = a.y; s1[4*q+2] = a.z; s1[4*q+3] = a.w;
        }
    }

    const uint32_t smb = (uint32_t)__cvta_generic_to_shared(sm);
    const uint32_t pqb = smb + SMTW * 4;
    __syncthreads();

    #pragma unroll 1
    for (int G = 0; G < 5; G++) {
        // ======== stage 1: lane -> col 4G+2w+cp, E/O sums for taus (g, g+16) ========
        const int cl = 2 * w + cp;                     // group-local col 0..3
        unsigned long long PE[8], PO[8], QE[8], QO[8];
        #pragma unroll
        for (int p = 0; p < 8; p++) { PE[p]=0; PO[p]=0; QE[p]=0; QO[p]=0; }

        const uint32_t colb = smb + (uint32_t)((4 * G + cl) * (TSTR * 4));
        #pragma unroll
        for (int f1 = 0; f1 < 16; f1++) {
            unsigned long long v[8];                   // S[16f1 + 0..15] as 8 f0-pairs
            #pragma unroll
            for (int q = 0; q < 4; q++)
                asm volatile("ld.shared.v2.b64 {%0, %1}, [%2];"
                             : "=l"(v[2*q]), "=l"(v[2*q+1])
                             : "r"(colb + f1 * 64 + q * 16));
            unsigned long long cpk, spk;
            PACK2(cpk, c1[f1]); PACK2(spk, s1[f1]);
            if ((f1 & 1) == 0) {
                #pragma unroll
                for (int p = 0; p < 8; p++) { FMA2(PE[p], cpk, v[p]); FMA2(QE[p], spk, v[p]); }
            } else {
                #pragma unroll
                for (int p = 0; p < 8; p++) { FMA2(PO[p], cpk, v[p]); FMA2(QO[p], spk, v[p]); }
            }
        }

        // ---- butterfly + PQ store: word = cl*1072 + u*33 + tau  (all 1-wavefront) ----
        const uint32_t pqc = pqb + (uint32_t)(cl * PQCOLW * 4) + (uint32_t)(g * 4);
        #pragma unroll
        for (int p = 0; p < 8; p++) {
            float pel = __uint_as_float((uint32_t)PE[p]), peh = __uint_as_float((uint32_t)(PE[p] >> 32));
            float pol = __uint_as_float((uint32_t)PO[p]), poh = __uint_as_float((uint32_t)(PO[p] >> 32));
            float qel = __uint_as_float((uint32_t)QE[p]), qeh = __uint_as_float((uint32_t)(QE[p] >> 32));
            float qol = __uint_as_float((uint32_t)QO[p]), qoh = __uint_as_float((uint32_t)(QO[p] >> 32));
            uint32_t a0 = pqc + (uint32_t)((2*p)      * 33 * 4);   // u = 2p
            uint32_t a1 = pqc + (uint32_t)((2*p + 1)  * 33 * 4);   // u = 2p+1
            uint32_t a2 = pqc + (uint32_t)((16 + 2*p) * 33 * 4);   // u = 16+2p
            uint32_t a3 = pqc + (uint32_t)((17 + 2*p) * 33 * 4);   // u = 17+2p
            asm volatile("st.shared.b32 [%0], %1;" :: "r"(a0),      "r"(__float_as_uint(pel + pol)));
            asm volatile("st.shared.b32 [%0], %1;" :: "r"(a0 + 64), "r"(__float_as_uint(pel - pol)));
            asm volatile("st.shared.b32 [%0], %1;" :: "r"(a1),      "r"(__float_as_uint(peh + poh)));
            asm volatile("st.shared.b32 [%0], %1;" :: "r"(a1 + 64), "r"(__float_as_uint(peh - poh)));
            asm volatile("st.shared.b32 [%0], %1;" :: "r"(a2),      "r"(__float_as_uint(qel + qol)));
            asm volatile("st.shared.b32 [%0], %1;" :: "r"(a2 + 64), "r"(__float_as_uint(qel - qol)));
            asm volatile("st.shared.b32 [%0], %1;" :: "r"(a3),      "r"(__float_as_uint(qeh + qoh)));
            asm volatile("st.shared.b32 [%0], %1;" :: "r"(a3 + 64), "r"(__float_as_uint(qeh - qoh)));
        }
        __syncthreads();

        // ======== stage 2: block-wide, 4 cols packed; t = tid + 64m ========
        unsigned long long z2[4][2];                   // [m][colpair]
        #pragma unroll
        for (int m = 0; m < 4; m++) { z2[m][0] = 0; z2[m][1] = 0; }
        const uint32_t pql = pqb + (uint32_t)((tid & 31) * 4);
        const float4* __restrict__ w2p = ((const float4*)g_w2) + tid;

        #pragma unroll 8
        for (int u = 0; u < 32; u++) {
            float4 w4 = __ldg(&w2p[u * 64]);
            uint32_t uoff = (uint32_t)(u * 33 * 4);
            uint32_t p0, p1, p2, p3;
            asm volatile("ld.shared.b32 %0, [%1];" : "=r"(p0) : "r"(pql + uoff));
            asm volatile("ld.shared.b32 %0, [%1];" : "=r"(p1) : "r"(pql + uoff + PQCOLW * 4));
            asm volatile("ld.shared.b32 %0, [%1];" : "=r"(p2) : "r"(pql + uoff + 2 * PQCOLW * 4));
            asm volatile("ld.shared.b32 %0, [%1];" : "=r"(p3) : "r"(pql + uoff + 3 * PQCOLW * 4));
            unsigned long long v01, v23;
            asm("mov.b64 %0, {%1, %2};" : "=l"(v01) : "r"(p0), "r"(p1));
            asm("mov.b64 %0, {%1, %2};" : "=l"(v23) : "r"(p2), "r"(p3));
            unsigned long long m0, m1, m2, m3;
            PACK2(m0, w4.x); PACK2(m1, w4.y); PACK2(m2, w4.z); PACK2(m3, w4.w);
            FMA2(z2[0][0], m0, v01); FMA2(z2[0][1], m0, v23);
            FMA2(z2[1][0], m1, v01); FMA2(z2[1][1], m1, v23);
            FMA2(z2[2][0], m2, v01); FMA2(z2[2][1], m2, v23);
            FMA2(z2[3][0], m3, v01); FMA2(z2[3][1], m3, v23);
        }

        // ---- Dt overlay into dead smT cols 4G..4G+3 ----
        #pragma unroll
        for (int m = 0; m < 4; m++) {
            int t = tid + 64 * m;
            sm[(4 * G)     * TSTR + t] = __uint_as_float((uint32_t)z2[m][0]);
            sm[(4 * G + 1) * TSTR + t] = __uint_as_float((uint32_t)(z2[m][0] >> 32));
            sm[(4 * G + 2) * TSTR + t] = __uint_as_float((uint32_t)z2[m][1]);
            sm[(4 * G + 3) * TSTR + t] = __uint_as_float((uint32_t)(z2[m][1] >> 32));
        }
        __syncthreads();                               // PQ reuse + Dt visibility
    }

    // ---- Windowed overlap-add epilogue: 4 consecutive k/thread, 18 segs ----
    {
        const int k0 = 4 * tid;                        // 0..252
        const bool lo = (tid < 32);                    // warp-uniform
        float wA[4], wB[4];
        #pragma unroll
        for (int d = 0; d < 4; d++) {
            int k = k0 + d;
            wA[d] = __ldg(&g_win[k]) * (lo ? -1.0f : 1.0f);
            wB[d] = __ldg(&g_win[k + 256]);
        }
        const int aOff = lo ? (124 - k0) : (k0 - 128); // word offset of zA quad
        const int bOff = lo ? (k0 + 128) : (380 - k0); // word offset of zB quad
        float* ob = out + (size_t)b * LOUT + k0;

        #pragma unroll 2
        for (int i = 0; i < NSEG; i++) {
            int s = s0 + i;
            if (s <= 4096) {
                float4 a4 = *reinterpret_cast<const float4*>(sm + (i + 1) * TSTR + aOff);
                float4 b4 = *reinterpret_cast<const float4*>(sm + i * TSTR + bOff);
                float av[4], bv[4];
                if (lo) { av[0]=a4.w; av[1]=a4.z; av[2]=a4.y; av[3]=a4.x;
                          bv[0]=b4.x; bv[1]=b4.y; bv[2]=b4.z; bv[3]=b4.w; }
                else    { av[0]=a4.x; av[1]=a4.y; av[2]=a4.z; av[3]=a4.w;
                          bv[0]=b4.w; bv[1]=b4.z; bv[2]=b4.y; bv[3]=b4.x; }
                float4 o;
                o.x = wA[0] * av[0] + wB[0] * bv[0];
                o.y = wA[1] * av[1] + wB[1] * bv[1];
                o.z = wA[2] * av[2] + wB[2] * bv[2];
                o.w = wA[3] * av[3] + wB[3] * bv[3];
                *reinterpret_cast<float4*>(ob + (size_t)s * 256) = o;
            }
        }
    }
}

extern "C" void kernel_launch(void* const* d_in, const int* in_sizes, int n_in,
                              void* d_out, int out_size)
{
    const float* spec    = (const float*)d_in[0];   // [16,1,256,4096]
    const float* kernels = (const float*)d_in[1];   // [512,256]
    float* out = (float*)d_out;                     // [16,1048832]

    prep_kernel<<<16, 256>>>(kernels);              // 4096 threads

    cudaFuncSetAttribute(imdct_main_kernel,
                         cudaFuncAttributeMaxDynamicSharedMemorySize, SMBYTES);
    dim3 grid((4097 + NSEG - 1) / NSEG, 16);        // (228, 16)
    imdct_main_kernel<<<grid, 64, SMBYTES>>>(spec, out);
}

// round 14
// speedup vs baseline: 2.3584x; 1.1414x over previous
#include <cuda_runtime.h>
#include <cstdint>
#include <math.h>

// IMDCT round 14 (= R13 with device-visible trig table): two-stage Cooley-Tukey;
// stage-1 f0-in-lane + compile-time immediate trig (FFMA-imm) + radix-2 tau butterfly;
// stage-2 4-col packed FMA2 (R12).
//
//   z_col[t] = sum_u W2[t][u]*PQ[u][tau], tau=t&31
//   PQ[f0][tau]    = sum_f1 S[16f1+f0]*cos(pi*f1*(2tau+1)/32)
//   PQ[16+f0][tau] = sum_f1 S[16f1+f0]*sin(pi*f1*(2tau+1)/32)
//   (angle mod 2pi -> CP64[f1*(2tau+1) & 63], sin = CP64[(k+48)&63])
//   butterfly: row tau+16 = (-1)^f1 * row tau  ->  E/O partial sums, P = E+-O.
// W2 from input kernels (validated R10-12). Epilogue: windowed overlap-add.
//
// Block 128 thr = 4 warps, NSEG=22, NCOLS=24 = 3 groups of 8 cols.

#define NFREQ    256
#define TFRAMES  4096
#define NSEG     22
#define NCOLS    24
#define TSTR     260                       // smT/Dt col stride (words)
#define SMTW     (NCOLS * TSTR)            // 6240 words
#define USTR     34                        // PQ u-stride (words)
#define PQCOLW   1104                      // PQ col stride (words); %32==16
#define SMWORDS  (SMTW + 8 * PQCOLW)       // 15072
#define SMBYTES  (SMWORDS * 4)             // 60,288 B
#define LOUT     1048832

#define FMA2(acc, a, v) \
    asm("fma.rn.f32x2 %0, %1, %2, %0;" : "+l"(acc) : "l"(a), "l"(v))
#define PACK2(dst, x) \
    asm("mov.b64 %0, {%1, %1};" : "=l"(dst) : "r"(__float_as_uint(x)))

// cos(k*pi/32), k = 0..63 — device-visible, constexpr-folded to FFMA immediates
// (all indices are compile-time constants after full unroll).
static __device__ constexpr float CP64[64] = {
     1.00000000f,  0.99518473f,  0.98078528f,  0.95694034f,
     0.92387953f,  0.88192126f,  0.83146961f,  0.77301045f,
     0.70710678f,  0.63439328f,  0.55557023f,  0.47139674f,
     0.38268343f,  0.29028468f,  0.19509032f,  0.09801714f,
     0.00000000f, -0.09801714f, -0.19509032f, -0.29028468f,
    -0.38268343f, -0.47139674f, -0.55557023f, -0.63439328f,
    -0.70710678f, -0.77301045f, -0.83146961f, -0.88192126f,
    -0.92387953f, -0.95694034f, -0.98078528f, -0.99518473f,
    -1.00000000f, -0.99518473f, -0.98078528f, -0.95694034f,
    -0.92387953f, -0.88192126f, -0.83146961f, -0.77301045f,
    -0.70710678f, -0.63439328f, -0.55557023f, -0.47139674f,
    -0.38268343f, -0.29028468f, -0.19509032f, -0.09801714f,
     0.00000000f,  0.09801714f,  0.19509032f,  0.29028468f,
     0.38268343f,  0.47139674f,  0.55557023f,  0.63439328f,
     0.70710678f,  0.77301045f,  0.83146961f,  0.88192126f,
     0.92387953f,  0.95694034f,  0.98078528f,  0.99518473f
};

__device__ float4 g_w2[32 * 64];    // [u][tid64]: {W2[t], W2[t+64], W2[t+128], W2[t+192]}
__device__ float  g_win[512];

__global__ void prep_kernel(const float* __restrict__ kernels)
{
    int idx = blockIdx.x * blockDim.x + threadIdx.x;   // 2560 threads
    if (idx < 2048) {                                  // g_w2
        int u = idx >> 6, tid = idx & 63;
        float r[4];
        #pragma unroll
        for (int m = 0; m < 4; m++) {
            int t = tid + 64 * m;
            double wn = sin(M_PI * (2.0 * (128 + t) + 1.0) / 1024.0);
            double sc = 1.0 / (128.0 * wn);
            if (u < 16)
                r[m] = (float)((double)kernels[(128 + t) * 256 + u] * sc);
            else {
                float sgn = (t & 1) ? 1.0f : -1.0f;    // -(-1)^t
                r[m] = sgn * (float)((double)kernels[(128 + t) * 256 + (255 - (u - 16))] * sc);
            }
        }
        g_w2[u * 64 + tid] = make_float4(r[0], r[1], r[2], r[3]);
    } else if (idx < 2560) {
        int t = idx - 2048;
        g_win[t] = (float)sin(M_PI * (2.0 * t + 1.0) / 1024.0);
    }
}

__global__ __launch_bounds__(128, 3)
void imdct_main_kernel(const float* __restrict__ spec, float* __restrict__ out)
{
    extern __shared__ float sm[];                      // smT[24][260] ++ PQ[8][1104]
    const int tid  = threadIdx.x;                      // 0..127
    const int lane = tid & 31;
    const int w    = tid >> 5;                         // warp 0..3
    const int cp   = lane >> 4;                        // stage-1 col select in warp
    const int f0   = lane & 15;                        // stage-1 u-base
    const int b    = blockIdx.y;
    const int s0   = blockIdx.x * NSEG;

    // ---- Stage spec transposed: smT[c][f] = spec[b][f][s0-1+c] ----
    const float* specB = spec + (size_t)b * NFREQ * TFRAMES;
    for (int i = tid; i < NFREQ * NCOLS; i += 128) {
        int f = i / NCOLS, c = i - f * NCOLS;
        int cg = s0 - 1 + c;
        float v = (cg >= 0 && cg < TFRAMES) ? __ldg(&specB[(size_t)f * TFRAMES + cg]) : 0.0f;
        sm[c * TSTR + f] = v;
    }

    const uint32_t smb = (uint32_t)__cvta_generic_to_shared(sm);
    const uint32_t pqb = smb + SMTW * 4;
    __syncthreads();

    #pragma unroll 1
    for (int G = 0; G < 3; G++) {
        // ======== stage 1: lane -> col 8G+2w+cp, all 32 taus for u = f0 / 16+f0 ========
        const int cl = 2 * w + cp;                     // group-local col 0..7
        const float* colp = sm + (8 * G + cl) * TSTR;

        float S[16];
        #pragma unroll
        for (int f1 = 0; f1 < 16; f1++) S[f1] = colp[16 * f1 + f0];

        const uint32_t pqP = pqb + (uint32_t)((cl * PQCOLW + f0 * USTR) * 4);
        const uint32_t pqQ = pqP + (uint32_t)(16 * USTR * 4);

        #pragma unroll
        for (int tp = 0; tp < 8; tp++) {               // taus 2tp, 2tp+1 (+16 via butterfly)
            float ep0 = 0.f, op0 = 0.f, eq0 = 0.f, oq0 = 0.f;
            float ep1 = 0.f, op1 = 0.f, eq1 = 0.f, oq1 = 0.f;
            #pragma unroll
            for (int f1 = 0; f1 < 16; f1++) {
                const int k0 = (f1 * (4 * tp + 1)) & 63;
                const int k1 = (f1 * (4 * tp + 3)) & 63;
                const float c0 = CP64[k0], s0c = CP64[(k0 + 48) & 63];
                const float c1 = CP64[k1], s1c = CP64[(k1 + 48) & 63];
                if (f1 & 1) {
                    op0 = fmaf(S[f1], c0, op0);  oq0 = fmaf(S[f1], s0c, oq0);
                    op1 = fmaf(S[f1], c1, op1);  oq1 = fmaf(S[f1], s1c, oq1);
                } else {
                    ep0 = fmaf(S[f1], c0, ep0);  eq0 = fmaf(S[f1], s0c, eq0);
                    ep1 = fmaf(S[f1], c1, ep1);  eq1 = fmaf(S[f1], s1c, eq1);
                }
            }
            // butterfly -> P[2tp..2tp+1], P[+16], Q[...], stored as b64 pairs
            unsigned long long Plo, Phi, Qlo, Qhi;
            asm("mov.b64 %0, {%1, %2};" : "=l"(Plo)
                : "r"(__float_as_uint(ep0 + op0)), "r"(__float_as_uint(ep1 + op1)));
            asm("mov.b64 %0, {%1, %2};" : "=l"(Phi)
                : "r"(__float_as_uint(ep0 - op0)), "r"(__float_as_uint(ep1 - op1)));
            asm("mov.b64 %0, {%1, %2};" : "=l"(Qlo)
                : "r"(__float_as_uint(eq0 + oq0)), "r"(__float_as_uint(eq1 + oq1)));
            asm("mov.b64 %0, {%1, %2};" : "=l"(Qhi)
                : "r"(__float_as_uint(eq0 - oq0)), "r"(__float_as_uint(eq1 - oq1)));
            asm volatile("st.shared.b64 [%0], %1;" :: "r"(pqP + 8 * tp),      "l"(Plo));
            asm volatile("st.shared.b64 [%0], %1;" :: "r"(pqP + 8 * tp + 64), "l"(Phi));
            asm volatile("st.shared.b64 [%0], %1;" :: "r"(pqQ + 8 * tp),      "l"(Qlo));
            asm volatile("st.shared.b64 [%0], %1;" :: "r"(pqQ + 8 * tp + 64), "l"(Qhi));
        }
        __syncthreads();

        // ======== stage 2: half-block (2 warps) per 4 cols; t = tid64 + 64m ========
        const int tid64 = tid & 63;
        const int cl0   = (tid >> 6) * 4;              // 0 or 4
        unsigned long long z2[4][2];
        #pragma unroll
        for (int m = 0; m < 4; m++) { z2[m][0] = 0; z2[m][1] = 0; }
        const uint32_t pql = pqb + (uint32_t)((cl0 * PQCOLW + (tid & 31)) * 4);
        const float4* __restrict__ w2p = ((const float4*)g_w2) + tid64;

        #pragma unroll 8
        for (int u = 0; u < 32; u++) {
            float4 w4 = __ldg(&w2p[u * 64]);
            uint32_t uoff = (uint32_t)(u * USTR * 4);
            uint32_t p0, p1, p2, p3;
            asm volatile("ld.shared.b32 %0, [%1];" : "=r"(p0) : "r"(pql + uoff));
            asm volatile("ld.shared.b32 %0, [%1];" : "=r"(p1) : "r"(pql + uoff + PQCOLW * 4));
            asm volatile("ld.shared.b32 %0, [%1];" : "=r"(p2) : "r"(pql + uoff + 2 * PQCOLW * 4));
            asm volatile("ld.shared.b32 %0, [%1];" : "=r"(p3) : "r"(pql + uoff + 3 * PQCOLW * 4));
            unsigned long long v01, v23;
            asm("mov.b64 %0, {%1, %2};" : "=l"(v01) : "r"(p0), "r"(p1));
            asm("mov.b64 %0, {%1, %2};" : "=l"(v23) : "r"(p2), "r"(p3));
            unsigned long long m0, m1, m2, m3;
            PACK2(m0, w4.x); PACK2(m1, w4.y); PACK2(m2, w4.z); PACK2(m3, w4.w);
            FMA2(z2[0][0], m0, v01); FMA2(z2[0][1], m0, v23);
            FMA2(z2[1][0], m1, v01); FMA2(z2[1][1], m1, v23);
            FMA2(z2[2][0], m2, v01); FMA2(z2[2][1], m2, v23);
            FMA2(z2[3][0], m3, v01); FMA2(z2[3][1], m3, v23);
        }

        // ---- Dt overlay into dead smT cols (8G+cl0 .. +3) ----
        const int ca = 8 * G + cl0;
        #pragma unroll
        for (int m = 0; m < 4; m++) {
            int t = tid64 + 64 * m;
            sm[(ca)     * TSTR + t] = __uint_as_float((uint32_t)z2[m][0]);
            sm[(ca + 1) * TSTR + t] = __uint_as_float((uint32_t)(z2[m][0] >> 32));
            sm[(ca + 2) * TSTR + t] = __uint_as_float((uint32_t)z2[m][1]);
            sm[(ca + 3) * TSTR + t] = __uint_as_float((uint32_t)(z2[m][1] >> 32));
        }
        __syncthreads();                               // PQ reuse + Dt visibility
    }

    // ---- Windowed overlap-add epilogue: 4 consecutive k/thread, 11 segs/thread ----
    {
        const int lt = tid & 63;
        const int h  = tid >> 6;                       // segment half
        const int k0 = 4 * lt;                         // 0..252
        const bool lo = (lt < 32);                     // warp-uniform
        float wA[4], wB[4];
        #pragma unroll
        for (int d = 0; d < 4; d++) {
            int k = k0 + d;
            wA[d] = __ldg(&g_win[k]) * (lo ? -1.0f : 1.0f);
            wB[d] = __ldg(&g_win[k + 256]);
        }
        const int aOff = lo ? (124 - k0) : (k0 - 128); // word offset of zA quad
        const int bOff = lo ? (k0 + 128) : (380 - k0); // word offset of zB quad
        float* ob = out + (size_t)b * LOUT + k0;

        #pragma unroll 2
        for (int ii = 0; ii < 11; ii++) {
            int i = 11 * h + ii;
            int s = s0 + i;
            if (s <= 4096) {
                float4 a4 = *reinterpret_cast<const float4*>(sm + (i + 1) * TSTR + aOff);
                float4 b4 = *reinterpret_cast<const float4*>(sm + i * TSTR + bOff);
                float av[4], bv[4];
                if (lo) { av[0]=a4.w; av[1]=a4.z; av[2]=a4.y; av[3]=a4.x;
                          bv[0]=b4.x; bv[1]=b4.y; bv[2]=b4.z; bv[3]=b4.w; }
                else    { av[0]=a4.x; av[1]=a4.y; av[2]=a4.z; av[3]=a4.w;
                          bv[0]=b4.w; bv[1]=b4.z; bv[2]=b4.y; bv[3]=b4.x; }
                float4 o;
                o.x = wA[0] * av[0] + wB[0] * bv[0];
                o.y = wA[1] * av[1] + wB[1] * bv[1];
                o.z = wA[2] * av[2] + wB[2] * bv[2];
                o.w = wA[3] * av[3] + wB[3] * bv[3];
                *reinterpret_cast<float4*>(ob + (size_t)s * 256) = o;
            }
        }
    }
}

extern "C" void kernel_launch(void* const* d_in, const int* in_sizes, int n_in,
                              void* d_out, int out_size)
{
    const float* spec    = (const float*)d_in[0];   // [16,1,256,4096]
    const float* kernels = (const float*)d_in[1];   // [512,256]
    float* out = (float*)d_out;                     // [16,1048832]

    prep_kernel<<<10, 256>>>(kernels);              // 2560 threads

    cudaFuncSetAttribute(imdct_main_kernel,
                         cudaFuncAttributeMaxDynamicSharedMemorySize, SMBYTES);
    dim3 grid((4097 + NSEG - 1) / NSEG, 16);        // (187, 16)
    imdct_main_kernel<<<grid, 128, SMBYTES>>>(spec, out);
}

// round 15
// speedup vs baseline: 2.8764x; 1.2196x over previous
#include <cuda_runtime.h>
#include <cstdint>
#include <math.h>

// IMDCT round 15: R14 structure, occupancy-tuned (NCOLS=16 -> 4 blocks/SM) + fp32 prep.
//
//   z_col[t] = sum_u W2[t][u]*PQ[u][tau], tau=t&31
//   PQ[f0][tau]    = sum_f1 S[16f1+f0]*cos(pi*f1*(2tau+1)/32)
//   PQ[16+f0][tau] = sum_f1 S[16f1+f0]*sin(pi*f1*(2tau+1)/32)
//   (angle mod 2pi -> CP64[f1*(2tau+1) & 63], sin = CP64[(k+48)&63])
//   butterfly: row tau+16 = (-1)^f1 * row tau  ->  E/O partial sums, P = E+-O.
// W2 from input kernels. Epilogue: windowed overlap-add.
//
// Block 128 thr = 4 warps, NSEG=14, NCOLS=16 = 2 groups of 8 cols.
// smem 51,456B -> 4 blocks/SM (16 warps).

#define NFREQ    256
#define TFRAMES  4096
#define NSEG     14
#define NCOLS    16
#define TSTR     260                       // smT/Dt col stride (words)
#define SMTW     (NCOLS * TSTR)            // 4160 words
#define USTR     34                        // PQ u-stride (words)
#define PQCOLW   1088                      // PQ col stride (words)
#define SMWORDS  (SMTW + 8 * PQCOLW)       // 12864
#define SMBYTES  (SMWORDS * 4)             // 51,456 B
#define LOUT     1048832

#define FMA2(acc, a, v) \
    asm("fma.rn.f32x2 %0, %1, %2, %0;" : "+l"(acc) : "l"(a), "l"(v))
#define PACK2(dst, x) \
    asm("mov.b64 %0, {%1, %1};" : "=l"(dst) : "r"(__float_as_uint(x)))

// cos(k*pi/32), k = 0..63 — folded to FFMA immediates (indices compile-time).
static __device__ constexpr float CP64[64] = {
     1.00000000f,  0.99518473f,  0.98078528f,  0.95694034f,
     0.92387953f,  0.88192126f,  0.83146961f,  0.77301045f,
     0.70710678f,  0.63439328f,  0.55557023f,  0.47139674f,
     0.38268343f,  0.29028468f,  0.19509032f,  0.09801714f,
     0.00000000f, -0.09801714f, -0.19509032f, -0.29028468f,
    -0.38268343f, -0.47139674f, -0.55557023f, -0.63439328f,
    -0.70710678f, -0.77301045f, -0.83146961f, -0.88192126f,
    -0.92387953f, -0.95694034f, -0.98078528f, -0.99518473f,
    -1.00000000f, -0.99518473f, -0.98078528f, -0.95694034f,
    -0.92387953f, -0.88192126f, -0.83146961f, -0.77301045f,
    -0.70710678f, -0.77301045f + 0.0f ? -0.63439328f : -0.63439328f, -0.55557023f, -0.47139674f,
    -0.38268343f, -0.29028468f, -0.19509032f, -0.09801714f,
     0.00000000f,  0.09801714f,  0.19509032f,  0.29028468f,
     0.38268343f,  0.47139674f,  0.55557023f,  0.63439328f,
     0.70710678f,  0.77301045f,  0.83146961f,  0.88192126f,
     0.92387953f,  0.95694034f,  0.98078528f,  0.99518473f
};

__device__ float4 g_w2[32 * 64];    // [u][tid64]: {W2[t], W2[t+64], W2[t+128], W2[t+192]}
__device__ float  g_win[512];

__global__ void prep_kernel(const float* __restrict__ kernels)
{
    int idx = blockIdx.x * blockDim.x + threadIdx.x;   // 2560 threads
    if (idx < 2048) {                                  // g_w2
        int u = idx >> 6, tid = idx & 63;
        float r[4];
        #pragma unroll
        for (int m = 0; m < 4; m++) {
            int t = tid + 64 * m;
            float wn = sinf((float)M_PI * (float)(2 * (128 + t) + 1) * (1.0f / 1024.0f));
            float sc = 1.0f / (128.0f * wn);
            if (u < 16)
                r[m] = kernels[(128 + t) * 256 + u] * sc;
            else {
                float sgn = (t & 1) ? 1.0f : -1.0f;    // -(-1)^t
                r[m] = sgn * kernels[(128 + t) * 256 + (255 - (u - 16))] * sc;
            }
        }
        g_w2[u * 64 + tid] = make_float4(r[0], r[1], r[2], r[3]);
    } else if (idx < 2560) {
        int t = idx - 2048;
        g_win[t] = sinf((float)M_PI * (float)(2 * t + 1) * (1.0f / 1024.0f));
    }
}

__global__ __launch_bounds__(128, 4)
void imdct_main_kernel(const float* __restrict__ spec, float* __restrict__ out)
{
    extern __shared__ float sm[];                      // smT[16][260] ++ PQ[8][1088]
    const int tid  = threadIdx.x;                      // 0..127
    const int lane = tid & 31;
    const int w    = tid >> 5;                         // warp 0..3
    const int cp   = lane >> 4;                        // stage-1 col select in warp
    const int f0   = lane & 15;                        // stage-1 u-base
    const int b    = blockIdx.y;
    const int s0   = blockIdx.x * NSEG;

    // ---- Stage spec transposed: smT[c][f] = spec[b][f][s0-1+c] ----
    const float* specB = spec + (size_t)b * NFREQ * TFRAMES;
    #pragma unroll 4
    for (int i = tid; i < NFREQ * NCOLS; i += 128) {
        int f = i >> 4, c = i & 15;
        int cg = s0 - 1 + c;
        float v = (cg >= 0 && cg < TFRAMES) ? __ldg(&specB[(size_t)f * TFRAMES + cg]) : 0.0f;
        sm[c * TSTR + f] = v;
    }

    const uint32_t smb = (uint32_t)__cvta_generic_to_shared(sm);
    const uint32_t pqb = smb + SMTW * 4;
    __syncthreads();

    #pragma unroll 1
    for (int G = 0; G < 2; G++) {
        // ======== stage 1: lane -> col 8G+2w+cp, all 32 taus for u = f0 / 16+f0 ========
        const int cl = 2 * w + cp;                     // group-local col 0..7
        const float* colp = sm + (8 * G + cl) * TSTR;

        float S[16];
        #pragma unroll
        for (int f1 = 0; f1 < 16; f1++) S[f1] = colp[16 * f1 + f0];

        const uint32_t pqP = pqb + (uint32_t)((cl * PQCOLW + f0 * USTR) * 4);
        const uint32_t pqQ = pqP + (uint32_t)(16 * USTR * 4);

        #pragma unroll
        for (int tp = 0; tp < 8; tp++) {               // taus 2tp, 2tp+1 (+16 via butterfly)
            float ep0 = 0.f, op0 = 0.f, eq0 = 0.f, oq0 = 0.f;
            float ep1 = 0.f, op1 = 0.f, eq1 = 0.f, oq1 = 0.f;
            #pragma unroll
            for (int f1 = 0; f1 < 16; f1++) {
                const int k0 = (f1 * (4 * tp + 1)) & 63;
                const int k1 = (f1 * (4 * tp + 3)) & 63;
                const float c0 = CP64[k0], s0c = CP64[(k0 + 48) & 63];
                const float c1 = CP64[k1], s1c = CP64[(k1 + 48) & 63];
                if (f1 & 1) {
                    op0 = fmaf(S[f1], c0, op0);  oq0 = fmaf(S[f1], s0c, oq0);
                    op1 = fmaf(S[f1], c1, op1);  oq1 = fmaf(S[f1], s1c, oq1);
                } else {
                    ep0 = fmaf(S[f1], c0, ep0);  eq0 = fmaf(S[f1], s0c, eq0);
                    ep1 = fmaf(S[f1], c1, ep1);  eq1 = fmaf(S[f1], s1c, eq1);
                }
            }
            // butterfly -> P[2tp..2tp+1], P[+16], Q[...], stored as b64 pairs
            unsigned long long Plo, Phi, Qlo, Qhi;
            asm("mov.b64 %0, {%1, %2};" : "=l"(Plo)
                : "r"(__float_as_uint(ep0 + op0)), "r"(__float_as_uint(ep1 + op1)));
            asm("mov.b64 %0, {%1, %2};" : "=l"(Phi)
                : "r"(__float_as_uint(ep0 - op0)), "r"(__float_as_uint(ep1 - op1)));
            asm("mov.b64 %0, {%1, %2};" : "=l"(Qlo)
                : "r"(__float_as_uint(eq0 + oq0)), "r"(__float_as_uint(eq1 + oq1)));
            asm("mov.b64 %0, {%1, %2};" : "=l"(Qhi)
                : "r"(__float_as_uint(eq0 - oq0)), "r"(__float_as_uint(eq1 - oq1)));
            asm volatile("st.shared.b64 [%0], %1;" :: "r"(pqP + 8 * tp),      "l"(Plo));
            asm volatile("st.shared.b64 [%0], %1;" :: "r"(pqP + 8 * tp + 64), "l"(Phi));
            asm volatile("st.shared.b64 [%0], %1;" :: "r"(pqQ + 8 * tp),      "l"(Qlo));
            asm volatile("st.shared.b64 [%0], %1;" :: "r"(pqQ + 8 * tp + 64), "l"(Qhi));
        }
        __syncthreads();

        // ======== stage 2: half-block (2 warps) per 4 cols; t = tid64 + 64m ========
        const int tid64 = tid & 63;
        const int cl0   = (tid >> 6) * 4;              // 0 or 4
        unsigned long long z2[4][2];
        #pragma unroll
        for (int m = 0; m < 4; m++) { z2[m][0] = 0; z2[m][1] = 0; }
        const uint32_t pql = pqb + (uint32_t)((cl0 * PQCOLW + (tid & 31)) * 4);
        const float4* __restrict__ w2p = ((const float4*)g_w2) + tid64;

        #pragma unroll 8
        for (int u = 0; u < 32; u++) {
            float4 w4 = __ldg(&w2p[u * 64]);
            uint32_t uoff = (uint32_t)(u * USTR * 4);
            uint32_t p0, p1, p2, p3;
            asm volatile("ld.shared.b32 %0, [%1];" : "=r"(p0) : "r"(pql + uoff));
            asm volatile("ld.shared.b32 %0, [%1];" : "=r"(p1) : "r"(pql + uoff + PQCOLW * 4));
            asm volatile("ld.shared.b32 %0, [%1];" : "=r"(p2) : "r"(pql + uoff + 2 * PQCOLW * 4));
            asm volatile("ld.shared.b32 %0, [%1];" : "=r"(p3) : "r"(pql + uoff + 3 * PQCOLW * 4));
            unsigned long long v01, v23;
            asm("mov.b64 %0, {%1, %2};" : "=l"(v01) : "r"(p0), "r"(p1));
            asm("mov.b64 %0, {%1, %2};" : "=l"(v23) : "r"(p2), "r"(p3));
            unsigned long long m0, m1, m2, m3;
            PACK2(m0, w4.x); PACK2(m1, w4.y); PACK2(m2, w4.z); PACK2(m3, w4.w);
            FMA2(z2[0][0], m0, v01); FMA2(z2[0][1], m0, v23);
            FMA2(z2[1][0], m1, v01); FMA2(z2[1][1], m1, v23);
            FMA2(z2[2][0], m2, v01); FMA2(z2[2][1], m2, v23);
            FMA2(z2[3][0], m3, v01); FMA2(z2[3][1], m3, v23);
        }

        // ---- Dt overlay into dead smT cols (8G+cl0 .. +3) ----
        const int ca = 8 * G + cl0;
        #pragma unroll
        for (int m = 0; m < 4; m++) {
            int t = tid64 + 64 * m;
            sm[(ca)     * TSTR + t] = __uint_as_float((uint32_t)z2[m][0]);
            sm[(ca + 1) * TSTR + t] = __uint_as_float((uint32_t)(z2[m][0] >> 32));
            sm[(ca + 2) * TSTR + t] = __uint_as_float((uint32_t)z2[m][1]);
            sm[(ca + 3) * TSTR + t] = __uint_as_float((uint32_t)(z2[m][1] >> 32));
        }
        __syncthreads();                               // PQ reuse + Dt visibility
    }

    // ---- Windowed overlap-add epilogue: 4 consecutive k/thread, 7 segs/thread ----
    {
        const int lt = tid & 63;
        const int h  = tid >> 6;                       // segment half
        const int k0 = 4 * lt;                         // 0..252
        const bool lo = (lt < 32);                     // warp-uniform
        float wA[4], wB[4];
        #pragma unroll
        for (int d = 0; d < 4; d++) {
            int k = k0 + d;
            wA[d] = __ldg(&g_win[k]) * (lo ? -1.0f : 1.0f);
            wB[d] = __ldg(&g_win[k + 256]);
        }
        const int aOff = lo ? (124 - k0) : (k0 - 128); // word offset of zA quad
        const int bOff = lo ? (k0 + 128) : (380 - k0); // word offset of zB quad
        float* ob = out + (size_t)b * LOUT + k0;

        #pragma unroll 2
        for (int ii = 0; ii < 7; ii++) {
            int i = 7 * h + ii;
            int s = s0 + i;
            if (s <= 4096) {
                float4 a4 = *reinterpret_cast<const float4*>(sm + (i + 1) * TSTR + aOff);
                float4 b4 = *reinterpret_cast<const float4*>(sm + i * TSTR + bOff);
                float av[4], bv[4];
                if (lo) { av[0]=a4.w; av[1]=a4.z; av[2]=a4.y; av[3]=a4.x;
                          bv[0]=b4.x; bv[1]=b4.y; bv[2]=b4.z; bv[3]=b4.w; }
                else    { av[0]=a4.x; av[1]=a4.y; av[2]=a4.z; av[3]=a4.w;
                          bv[0]=b4.w; bv[1]=b4.z; bv[2]=b4.y; bv[3]=b4.x; }
                float4 o;
                o.x = wA[0] * av[0] + wB[0] * bv[0];
                o.y = wA[1] * av[1] + wB[1] * bv[1];
                o.z = wA[2] * av[2] + wB[2] * bv[2];
                o.w = wA[3] * av[3] + wB[3] * bv[3];
                *reinterpret_cast<float4*>(ob + (size_t)s * 256) = o;
            }
        }
    }
}

extern "C" void kernel_launch(void* const* d_in, const int* in_sizes, int n_in,
                              void* d_out, int out_size)
{
    const float* spec    = (const float*)d_in[0];   // [16,1,256,4096]
    const float* kernels = (const float*)d_in[1];   // [512,256]
    float* out = (float*)d_out;                     // [16,1048832]

    prep_kernel<<<10, 256>>>(kernels);              // 2560 threads, fp32

    cudaFuncSetAttribute(imdct_main_kernel,
                         cudaFuncAttributeMaxDynamicSharedMemorySize, SMBYTES);
    dim3 grid((4097 + NSEG - 1) / NSEG, 16);        // (293, 16)
    imdct_main_kernel<<<grid, 128, SMBYTES>>>(spec, out);
}